// round 8
// baseline (speedup 1.0000x reference)
#include <cuda_runtime.h>
#include <cuda_bf16.h>

// Problem constants
#define B_     32
#define CIN    64
#define H_     64
#define W_     64
#define COUT   128
#define CONN   4
#define KHW    9
#define RROWS  4               // output rows per block stripe
#define SROWS  (RROWS+2)       // 6 shared rows incl. halo (di in 0..2)
#define NTHREADS 512
#define NSTRIPES (H_ / RROWS)  // 16

// Row layout: stride 68 floats. Row k base = 4 + 68k.
//   base-1      = left halo (copy of col 0)
//   base+0..63  = cols 0..63 (float4-aligned stores)
//   base+64     = right halo (copy of col 63)
#define RSTRIDE 68
#define XS_FLOATS (4 + CIN * SROWS * RSTRIDE)   // 26116
#define XS_BYTES  (XS_FLOATS * 4)               // 104464 (16B-aligned)
#define TBL_OFF   (XS_BYTES)                    // float2[512]: 4096 B
#define BSH_OFF   (TBL_OFF + 4096)              // float[128]: 512 B
#define SMEM_TOTAL (BSH_OFF + 512)              // 109072 B -> 2 CTAs/SM

__global__ void __launch_bounds__(NTHREADS, 2)
lp_conv2d_bt_kernel(const float* __restrict__ x,
                    const float* __restrict__ wts,
                    const float* __restrict__ bias,
                    const int*   __restrict__ conn,
                    float* __restrict__ out)
{
    extern __shared__ float xs[];
    float2* tbl = (float2*)((char*)xs + TBL_OFF);
    float*  bsh = (float*)((char*)xs + BSH_OFF);

    const int tid = threadIdx.x;
    const int s   = blockIdx.x;   // stripe 0..15
    const int b   = blockIdx.y;   // batch 0..31

    // ---- Decode conn table: 512 (o,j) entries, one per thread ----
    {
        int idx = conn[tid];               // 0 .. CIN*KHW-1
        int c   = idx / KHW;
        int rem = idx - c * KHW;
        int di  = rem / 3;
        int dj  = rem - di * 3;
        float2 t;
        t.x = wts[tid];
        // addr = xs + off + col ; off = rowbase(3) + dj + (c*SROWS+di)*RSTRIDE
        t.y = __uint_as_float((unsigned)((c * SROWS + di) * RSTRIDE + dj + 3));
        tbl[tid] = t;
        if (tid < COUT) bsh[tid] = bias[tid];
    }

    // ---- Stage input stripe: 64 ch x 6 rows (edge-clamped rows) ----
    const int i0 = s * RROWS;
    const float4* __restrict__ xsrc =
        (const float4*)(x + (size_t)b * (CIN * H_ * W_));
    #pragma unroll
    for (int it = 0; it < (CIN * SROWS * (W_/4)) / NTHREADS; it++) {   // 12 iters
        int idx = tid + it * NTHREADS;
        int ch  = idx / (SROWS * (W_/4));       // /96
        int rem = idx - ch * (SROWS * (W_/4));
        int r   = rem >> 4;                     // shared row 0..5
        int c4  = rem & 15;
        int gr  = i0 - 1 + r;
        gr = max(0, min(H_ - 1, gr));           // edge padding = row clamp
        float4 v = xsrc[(ch * H_ + gr) * (W_/4) + c4];
        float* base = xs + 4 + (ch * SROWS + r) * RSTRIDE;
        *(float4*)(base + 4 * c4) = v;          // aligned STS.128
        if (c4 == 0)  base[-1] = v.x;           // left halo  = col 0
        if (c4 == 15) base[64] = v.w;           // right halo = col 63
    }
    __syncthreads();

    // ---- Compute: lane = column; slot owns 16 o's; o-pairs pipelined ----
    const int col  = tid & 63;
    const int slot = tid >> 6;                  // 0..7
    const int o0   = slot * 16;

    const float* xcol = xs + col;
    float* outbase = out + (((size_t)(b * COUT + o0)) * H_ + i0) * W_ + col;
    const float4* q = (const float4*)(tbl + o0 * CONN);  // 2 float4 per o

#define TAP(tw, toff, ma, mb, mc, md)                           \
    {                                                           \
        const float  w_ = (tw);                                 \
        const float* p_ = xcol + __float_as_uint(toff);         \
        ma = fmaxf(ma, fabsf(w_ - p_[0 * RSTRIDE]));            \
        mb = fmaxf(mb, fabsf(w_ - p_[1 * RSTRIDE]));            \
        mc = fmaxf(mc, fabsf(w_ - p_[2 * RSTRIDE]));            \
        md = fmaxf(md, fabsf(w_ - p_[3 * RSTRIDE]));            \
    }

    // Prologue: prefetch tables for pair 0 (o0, o0+1)
    float4 ta0 = q[0], ta1 = q[1];   // o even: taps 0-1, 2-3
    float4 tb0 = q[2], tb1 = q[3];   // o odd

    #pragma unroll
    for (int ko = 0; ko < 8; ko++) {
        // Prefetch next pair's tables ((ko+1)&7 wraps harmlessly on last iter)
        const int np = ((ko + 1) & 7) * 4;
        float4 na0 = q[np + 0], na1 = q[np + 1];
        float4 nb0 = q[np + 2], nb1 = q[np + 3];

        float a0 = 0.f, a1 = 0.f, a2 = 0.f, a3 = 0.f;   // o = o0+2ko
        float b0 = 0.f, b1 = 0.f, b2 = 0.f, b3 = 0.f;   // o = o0+2ko+1

        TAP(ta0.x, ta0.y, a0, a1, a2, a3)
        TAP(ta0.z, ta0.w, a0, a1, a2, a3)
        TAP(ta1.x, ta1.y, a0, a1, a2, a3)
        TAP(ta1.z, ta1.w, a0, a1, a2, a3)
        TAP(tb0.x, tb0.y, b0, b1, b2, b3)
        TAP(tb0.z, tb0.w, b0, b1, b2, b3)
        TAP(tb1.x, tb1.y, b0, b1, b2, b3)
        TAP(tb1.z, tb1.w, b0, b1, b2, b3)

        const float bva = bsh[o0 + 2 * ko];
        const float bvb = bsh[o0 + 2 * ko + 1];
        float* pa = outbase + (size_t)(2 * ko) * (H_ * W_);
        float* pb = pa + (H_ * W_);
        pa[0 * W_] = a0 + bva;  pa[1 * W_] = a1 + bva;
        pa[2 * W_] = a2 + bva;  pa[3 * W_] = a3 + bva;
        pb[0 * W_] = b0 + bvb;  pb[1 * W_] = b1 + bvb;
        pb[2 * W_] = b2 + bvb;  pb[3 * W_] = b3 + bvb;

        ta0 = na0; ta1 = na1; tb0 = nb0; tb1 = nb1;
    }
#undef TAP
}

extern "C" void kernel_launch(void* const* d_in, const int* in_sizes, int n_in,
                              void* d_out, int out_size)
{
    const float* x    = (const float*)d_in[0];   // [32,64,64,64]
    const float* wts  = (const float*)d_in[1];   // [128,4]
    const float* bias = (const float*)d_in[2];   // [128,1,1]
    const int*   conn = (const int*)d_in[3];     // [128,4] int32
    float* out = (float*)d_out;                  // [32,128,64,64]

    static_assert(2 * SMEM_TOTAL <= 227 * 1024, "want 2 CTAs/SM");
    cudaFuncSetAttribute(lp_conv2d_bt_kernel,
                         cudaFuncAttributeMaxDynamicSharedMemorySize, SMEM_TOTAL);

    dim3 grid(NSTRIPES, B_);
    lp_conv2d_bt_kernel<<<grid, NTHREADS, SMEM_TOTAL>>>(x, wts, bias, conn, out);
}